// round 15
// baseline (speedup 1.0000x reference)
#include <cuda_runtime.h>
#include <cuda_fp16.h>
#include <cuda_fp8.h>
#include <math.h>

// Problem constants (fixed-shape problem)
static constexpr int N_USER  = 100000;
static constexpr int N_ITEM  = 50000;
static constexpr int NN      = N_USER + N_ITEM;   // 150000
static constexpr int D       = 64;
static constexpr int ROWB    = 128;               // row bytes: 64 int + 64 pop e4m3
static constexpr int E_EDGES = 2000000;
static constexpr int BATCH   = 8192;

static constexpr int SCAN_CHUNK = 1024;
static constexpr int NB_SCAN = (NN + SCAN_CHUNK - 1) / SCAN_CHUNK;  // 147

// All fp8 buffers store 16x the true value (descaled in k_score).
// ---------------- device scratch (static globals, no allocation) -------------
__device__ int    g_dego[NN];
__device__ int    g_degi[NN];
__device__ int    g_rowptr[NN];
__device__ int    g_cursor[NN];
__device__ int    g_bsum[NB_SCAN];
__device__ int    g_dhist[256];        // degree histogram (clamped)
__device__ int    g_dcur[256];         // bucket cursors (DESCENDING-degree layout)
__device__ int    g_order[NN];         // nodes sorted by in-degree, LARGEST FIRST
__device__ int    g_csr[E_EDGES];      // src node only (norm factored out)
__device__ unsigned char g_need[NN];   // layer-3 pruning flags (sampled nodes)
__device__ unsigned char g_need2[NN];  // layer-2 flags: need ∪ sources(need)
__device__ unsigned char g_E[(size_t)NN * ROWB];   // 16*rdo*emb  (e4m3)
__device__ unsigned char g_A[(size_t)NN * ROWB];
__device__ unsigned char g_B[(size_t)NN * ROWB];
__device__ unsigned char g_C[(size_t)NN * ROWB];
__device__ double g_sums[4];
__device__ int    g_mask_is_u8;
__device__ unsigned g_done;            // score last-block ticket

// ---------------- helpers ----------------------------------------------------
__device__ __forceinline__ float softplus_f(float x) {
    return fmaxf(x, 0.0f) + log1pf(expf(-fabsf(x)));
}
__device__ __forceinline__ float logsig_f(float x) {
    return fminf(x, 0.0f) - log1pf(expf(-fabsf(x)));
}
// acch[8] (half2) += 16 e4m3 values packed in uint4
__device__ __forceinline__ void acc_fp8_16(__half2* acch, uint4 raw) {
    #pragma unroll
    for (int k = 0; k < 4; k++) {
        unsigned w = (&raw.x)[k];
        __half2_raw h0 = __nv_cvt_fp8x2_to_halfraw2((__nv_fp8x2_storage_t)(w & 0xFFFFu), __NV_E4M3);
        __half2_raw h1 = __nv_cvt_fp8x2_to_halfraw2((__nv_fp8x2_storage_t)(w >> 16), __NV_E4M3);
        acch[2*k]   = __hadd2(acch[2*k],   *reinterpret_cast<__half2*>(&h0));
        acch[2*k+1] = __hadd2(acch[2*k+1], *reinterpret_cast<__half2*>(&h1));
    }
}
__device__ __forceinline__ float2 fp8x2_to_float2(unsigned short v) {
    __half2_raw h = __nv_cvt_fp8x2_to_halfraw2((__nv_fp8x2_storage_t)v, __NV_E4M3);
    return __half22float2(*reinterpret_cast<__half2*>(&h));
}

// ---------------- kernels ----------------------------------------------------
// Zero degrees / flags / sums / histogram / ticket.
__global__ void k_init() {
    int i = blockIdx.x * blockDim.x + threadIdx.x;
    if (i < NN) { g_dego[i] = 0; g_degi[i] = 0; g_need[i] = 0; g_need2[i] = 0; }
    if (i < 256) g_dhist[i] = 0;
    if (i < 4)  g_sums[i] = 0.0;
    if (i == 0) { g_mask_is_u8 = 0; g_done = 0; }
}

// Degree counting + mask-layout detect + layer-3 need flags.
__global__ void k_degree(const int* __restrict__ es, const int* __restrict__ ed,
                         const unsigned char* __restrict__ m,
                         const int* __restrict__ user, const int* __restrict__ itp,
                         const int* __restrict__ itn) {
    int i = blockIdx.x * blockDim.x + threadIdx.x;
    if (i < BATCH) {
        if ((i & 3) && m[i]) atomicOr(&g_mask_is_u8, 1);
        g_need[user[i]] = 1;
        g_need[itp[i] + N_USER] = 1;
        g_need[itn[i] + N_USER] = 1;
    }
    if (i >= E_EDGES) return;
    atomicAdd(&g_dego[es[i]], 1);
    atomicAdd(&g_degi[ed[i]], 1);
}

// Per-chunk sums of g_degi + block-aggregated degree histogram.
__global__ void k_scan_a() {
    __shared__ int sdata[256];
    __shared__ int shist[256];
    int base = blockIdx.x * SCAN_CHUNK;
    int t = threadIdx.x;
    shist[t] = 0;
    __syncthreads();
    int s = 0;
    #pragma unroll
    for (int j = 0; j < 4; j++) {
        int idx = base + t * 4 + j;
        if (idx < NN) {
            int d = g_degi[idx];
            s += d;
            atomicAdd(&shist[min(d, 255)], 1);
        }
    }
    sdata[t] = s;
    __syncthreads();
    for (int off = 128; off > 0; off >>= 1) {
        if (t < off) sdata[t] += sdata[t + off];
        __syncthreads();
    }
    if (t == 0) g_bsum[blockIdx.x] = sdata[0];
    if (shist[t]) atomicAdd(&g_dhist[t], shist[t]);
}

// Fused: blocks [0, NB_SCAN) build rowptr/cursor; block NB_SCAN scans the
// degree histogram; ALL blocks run grid-stride fp32 -> e4m3 (x16*rdo) convert.
__global__ void k_scan_bc_convert(const float* __restrict__ ei, const float* __restrict__ ep) {
    __shared__ int sb[256];
    __shared__ int sdata[256];
    int t = threadIdx.x;

    if (blockIdx.x < NB_SCAN) {
        sb[t] = (t < NB_SCAN) ? g_bsum[t] : 0;
        __syncthreads();
        for (int off = 1; off < 256; off <<= 1) {
            int tmp = (t >= off) ? sb[t - off] : 0;
            __syncthreads();
            sb[t] += tmp;
            __syncthreads();
        }
        int boff = (blockIdx.x == 0) ? 0 : sb[blockIdx.x - 1];

        int base = blockIdx.x * SCAN_CHUNK;
        int v[4];
        int tsum = 0;
        #pragma unroll
        for (int j = 0; j < 4; j++) {
            int idx = base + t * 4 + j;
            v[j] = (idx < NN) ? g_degi[idx] : 0;
            tsum += v[j];
        }
        sdata[t] = tsum;
        __syncthreads();
        for (int off = 1; off < 256; off <<= 1) {
            int tmp = (t >= off) ? sdata[t - off] : 0;
            __syncthreads();
            sdata[t] += tmp;
            __syncthreads();
        }
        int run = sdata[t] - tsum + boff;
        #pragma unroll
        for (int j = 0; j < 4; j++) {
            int idx = base + t * 4 + j;
            if (idx < NN) {
                g_rowptr[idx] = run;
                g_cursor[idx] = run;
                run += v[j];
            }
        }
    } else if (blockIdx.x == NB_SCAN) {
        // DESCENDING bucket layout (LPT schedule): bucket b starts after all
        // higher-degree buckets: start(b) = total - inclusive_prefix(b).
        int v = g_dhist[t];
        sb[t] = v;
        __syncthreads();
        for (int off = 1; off < 256; off <<= 1) {
            int tmp = (t >= off) ? sb[t - off] : 0;
            __syncthreads();
            sb[t] += tmp;
            __syncthreads();
        }
        int total = sb[255];
        g_dcur[t] = total - sb[t];
    }

    // convert: each item = 8 e4m3 bytes (uint2). NN*16 items.
    int total = NN * 16;
    for (int i = blockIdx.x * blockDim.x + threadIdx.x; i < total;
         i += gridDim.x * blockDim.x) {
        int node = i >> 4;
        int sub  = i & 15;
        int eo   = sub * 8;       // element (=byte) offset within 128-row
        float sc = 16.0f * rsqrtf(fmaxf((float)g_dego[node], 1.0f));
        const float* s = (eo < 64) ? (ei + (size_t)node * D + eo)
                                   : (ep + (size_t)node * D + (eo - 64));
        float4 v0 = *reinterpret_cast<const float4*>(s);
        float4 v1 = *reinterpret_cast<const float4*>(s + 4);
        unsigned a0 = __nv_cvt_float2_to_fp8x2(make_float2(v0.x * sc, v0.y * sc), __NV_SATFINITE, __NV_E4M3);
        unsigned a1 = __nv_cvt_float2_to_fp8x2(make_float2(v0.z * sc, v0.w * sc), __NV_SATFINITE, __NV_E4M3);
        unsigned a2 = __nv_cvt_float2_to_fp8x2(make_float2(v1.x * sc, v1.y * sc), __NV_SATFINITE, __NV_E4M3);
        unsigned a3 = __nv_cvt_float2_to_fp8x2(make_float2(v1.z * sc, v1.w * sc), __NV_SATFINITE, __NV_E4M3);
        uint2 ow;
        ow.x = (a0 & 0xFFFFu) | (a1 << 16);
        ow.y = (a2 & 0xFFFFu) | (a3 << 16);
        *reinterpret_cast<uint2*>(g_E + (size_t)node * ROWB + eo) = ow;
    }
}

// Edge placement + descending-degree node order scatter + edge-parallel need2:
// need2 = need ∪ {src : dst(need)}. One predicated byte op per edge, fused.
__global__ void k_place(const int* __restrict__ es, const int* __restrict__ ed) {
    int i = blockIdx.x * blockDim.x + threadIdx.x;
    if (i < E_EDGES) {
        int s = es[i];
        int d = ed[i];
        int pos = atomicAdd(&g_cursor[d], 1);
        g_csr[pos] = s;
        if (g_need[d]) g_need2[s] = 1;
    }
    if (i < NN) {
        int b = min(g_degi[i], 255);
        int pos = atomicAdd(&g_dcur[b], 1);
        g_order[pos] = i;
        if (g_need[i]) g_need2[i] = 1;
    }
}

// CSR gather: 8 lanes per node, 4 nodes per warp, degree-sorted node order
// (largest-degree first — LPT). Row = 128B e4m3 (one line); each lane loads
// uint4 (16 fp8 = 16B). CSR indices loaded uniformly per group (hardware
// broadcast), NO shuffles. 8->4->1 unroll cascade (frozen inner loop form).
// prune: 0 none, 1 -> g_need, 2 -> g_need2.
__global__ void __launch_bounds__(256)
k_gather(const unsigned char* __restrict__ src, unsigned char* __restrict__ dst, int prune) {
    unsigned t = blockIdx.x * blockDim.x + threadIdx.x;
    unsigned warp = t >> 5;
    unsigned lane = t & 31u;
    unsigned grp  = lane >> 3;      // 0..3
    unsigned gl   = lane & 7u;      // lane within group
    unsigned idx  = warp * 4 + grp;
    if (idx >= (unsigned)NN) return;
    int node = g_order[idx];
    if (prune == 1 && !g_need[node]) return;
    if (prune == 2 && !g_need2[node]) return;

    const int c = (int)gl * 16;     // byte offset within 128B row

    int start = g_rowptr[node];
    int cnt   = g_degi[node];

    __half2 zz = __floats2half2_rn(0.f, 0.f);
    __half2 acch[8] = { zz, zz, zz, zz, zz, zz, zz, zz };

    int j = 0;
    // 8-wide main loop: 8 CSR loads + 8 row loads issued before accumulation.
    for (; j + 8 <= cnt; j += 8) {
        int si[8];
        #pragma unroll
        for (int u = 0; u < 8; u++) si[u] = __ldg(&g_csr[start + j + u]);
        uint4 rr[8];
        #pragma unroll
        for (int u = 0; u < 8; u++)
            rr[u] = __ldg(reinterpret_cast<const uint4*>(src + (size_t)si[u] * ROWB + c));
        #pragma unroll
        for (int u = 0; u < 8; u++) acc_fp8_16(acch, rr[u]);
    }
    // 4-wide step
    for (; j + 4 <= cnt; j += 4) {
        int s0 = __ldg(&g_csr[start + j + 0]);
        int s1 = __ldg(&g_csr[start + j + 1]);
        int s2 = __ldg(&g_csr[start + j + 2]);
        int s3 = __ldg(&g_csr[start + j + 3]);
        uint4 r0 = __ldg(reinterpret_cast<const uint4*>(src + (size_t)s0 * ROWB + c));
        uint4 r1 = __ldg(reinterpret_cast<const uint4*>(src + (size_t)s1 * ROWB + c));
        uint4 r2 = __ldg(reinterpret_cast<const uint4*>(src + (size_t)s2 * ROWB + c));
        uint4 r3 = __ldg(reinterpret_cast<const uint4*>(src + (size_t)s3 * ROWB + c));
        acc_fp8_16(acch, r0);
        acc_fp8_16(acch, r1);
        acc_fp8_16(acch, r2);
        acc_fp8_16(acch, r3);
    }
    // scalar tail
    for (; j < cnt; j++) {
        int sj = __ldg(&g_csr[start + j]);
        uint4 rv = __ldg(reinterpret_cast<const uint4*>(src + (size_t)sj * ROWB + c));
        acc_fp8_16(acch, rv);
    }

    float rs = rsqrtf(fmaxf((float)g_dego[node], 1.0f))
             * rsqrtf(fmaxf((float)g_degi[node], 1.0f));
    uint4 outw;
    #pragma unroll
    for (int k = 0; k < 4; k++) {
        float2 f0 = __half22float2(acch[2*k]);
        float2 f1 = __half22float2(acch[2*k+1]);
        unsigned o0 = __nv_cvt_float2_to_fp8x2(make_float2(f0.x * rs, f0.y * rs),
                                               __NV_SATFINITE, __NV_E4M3);
        unsigned o1 = __nv_cvt_float2_to_fp8x2(make_float2(f1.x * rs, f1.y * rs),
                                               __NV_SATFINITE, __NV_E4M3);
        (&outw.x)[k] = (o0 & 0xFFFFu) | (o1 << 16);
    }
    *reinterpret_cast<uint4*>(dst + (size_t)node * ROWB + c) = outw;
}

// One warp per triple. f-row (x4) = e0 + (sqrt(dego)/16) * (S_A + S_B + S_C).
// Dots scale by 1/16. Final reduction: last block writes the loss.
__global__ void __launch_bounds__(256)
k_score(const float* __restrict__ ei, const float* __restrict__ ep,
        const float* __restrict__ q, const float* __restrict__ bq,
        const int* __restrict__ user, const int* __restrict__ itp,
        const int* __restrict__ itn, const void* __restrict__ mask,
        float* __restrict__ out, int nblocks) {
    int t = blockIdx.x * blockDim.x + threadIdx.x;
    int w = t >> 5;
    int lane = t & 31;
    int wib = (threadIdx.x >> 5);
    __shared__ float sred[8][4];

    float s0 = 0.f, s1 = 0.f, s2 = 0.f, s3 = 0.f;
    if (w < BATCH) {
        int u  = user[w];
        int p  = itp[w];
        int n  = itn[w];

        auto rowsum = [&](const float* e, int node, int pop) -> float2 {
            size_t re = (size_t)node * D;
            size_t rh = (size_t)node * ROWB + pop * 64 + lane * 2;
            float sq = sqrtf(fmaxf((float)g_dego[node], 1.0f)) * 0.0625f;
            float2 x = reinterpret_cast<const float2*>(e + re)[lane];
            float2 fa = fp8x2_to_float2(*reinterpret_cast<const unsigned short*>(g_A + rh));
            float2 fb = fp8x2_to_float2(*reinterpret_cast<const unsigned short*>(g_B + rh));
            float2 fc = fp8x2_to_float2(*reinterpret_cast<const unsigned short*>(g_C + rh));
            return make_float2(x.x + sq * (fa.x + fb.x + fc.x),
                               x.y + sq * (fa.y + fb.y + fc.y));
        };

        int np = p + N_USER;
        int nn = n + N_USER;
        float2 a  = rowsum(ei, u, 0);
        float2 bb = rowsum(ep, u, 1);
        float2 cp = rowsum(ei, np, 0);
        float2 dp = rowsum(ep, np, 1);
        float2 cn = rowsum(ei, nn, 0);
        float2 dn = rowsum(ep, nn, 1);

        float pint = a.x * cp.x + a.y * cp.y;
        float nint = a.x * cn.x + a.y * cn.y;
        float ppop = bb.x * dp.x + bb.y * dp.y;
        float npop = bb.x * dn.x + bb.y * dn.y;

        #pragma unroll
        for (int o = 16; o > 0; o >>= 1) {
            pint += __shfl_xor_sync(0xffffffffu, pint, o);
            nint += __shfl_xor_sync(0xffffffffu, nint, o);
            ppop += __shfl_xor_sync(0xffffffffu, ppop, o);
            npop += __shfl_xor_sync(0xffffffffu, npop, o);
        }

        if (lane == 0) {
            const float inv16 = 0.0625f;
            pint *= inv16; nint *= inv16; ppop *= inv16; npop *= inv16;

            bool m;
            if (g_mask_is_u8)
                m = ((const unsigned char*)mask)[w] != 0;
            else
                m = ((const int*)mask)[w] != 0;
            float mf = m ? 1.0f : 0.0f;
            float nmf = 1.0f - mf;

            s0 = mf  * logsig_f(pint - nint);
            s1 = mf  * logsig_f(npop - ppop);
            s2 = nmf * logsig_f(ppop - npop);

            float popp = softplus_f(q[p]) + softplus_f(bq[p]);
            float popn = softplus_f(q[n]) + softplus_f(bq[n]);
            float ptot = pint + ppop;
            float ntot = nint + npop;
            s3 = logsig_f(tanhf(popp) * ptot - tanhf(popn) * ntot);
        }
    }
    if (lane == 0) {
        sred[wib][0] = s0; sred[wib][1] = s1; sred[wib][2] = s2; sred[wib][3] = s3;
    }
    __syncthreads();
    if (threadIdx.x < 4) {
        float tsum = 0.f;
        #pragma unroll
        for (int k = 0; k < 8; k++) tsum += sred[k][threadIdx.x];
        atomicAdd(&g_sums[threadIdx.x], (double)tsum);
    }
    // last-block ticket writes the final loss
    __syncthreads();
    if (threadIdx.x == 0) {
        __threadfence();
        unsigned ticket = atomicAdd(&g_done, 1u);
        if (ticket == (unsigned)(nblocks - 1)) {
            double invB = 1.0 / (double)BATCH;
            double loss_int  = -g_sums[0] * invB;
            double loss_pop  = (-g_sums[1] + g_sums[2]) * invB;
            double loss_tide = -g_sums[3] * invB;
            out[0] = (float)(0.1 * loss_int + 0.1 * loss_pop + 0.2 * loss_tide);
        }
    }
}

// ---------------- launch ------------------------------------------------------
extern "C" void kernel_launch(void* const* d_in, const int* in_sizes, int n_in,
                              void* d_out, int out_size) {
    const float* emb_int = (const float*)d_in[0];
    const float* emb_pop = (const float*)d_in[1];
    const float* q       = (const float*)d_in[2];
    const float* bq      = (const float*)d_in[3];
    const int*   user    = (const int*)d_in[4];
    const int*   itp     = (const int*)d_in[5];
    const int*   itn     = (const int*)d_in[6];
    const void*  mask    = d_in[7];
    const int*   es      = (const int*)d_in[8];
    const int*   ed      = (const int*)d_in[9];
    float* out = (float*)d_out;

    const int TB = 256;
    int gridE  = (E_EDGES + TB - 1) / TB;
    int gridN  = (NN + TB - 1) / TB;
    int gridC  = (NN * 16 + TB - 1) / TB;
    long long warpsG = (NN + 3) / 4;
    int gridG  = (int)((warpsG * 32 + TB - 1) / TB);
    int gridS  = (BATCH * 32 + TB - 1) / TB;

    unsigned char *E, *A, *B, *C;
    cudaGetSymbolAddress((void**)&E, g_E);
    cudaGetSymbolAddress((void**)&A, g_A);
    cudaGetSymbolAddress((void**)&B, g_B);
    cudaGetSymbolAddress((void**)&C, g_C);

    k_init<<<gridN, TB>>>();
    k_degree<<<gridE, TB>>>(es, ed, (const unsigned char*)mask, user, itp, itn);
    k_scan_a<<<NB_SCAN, 256>>>();
    k_scan_bc_convert<<<gridC, 256>>>(emb_int, emb_pop);
    k_place<<<gridE, TB>>>(es, ed);

    k_gather<<<gridG, TB>>>(E, A, 0);   // layer 1
    k_gather<<<gridG, TB>>>(A, B, 2);   // layer 2 (need2-pruned, edge-parallel flags)
    k_gather<<<gridG, TB>>>(B, C, 1);   // layer 3 (need-pruned)

    k_score<<<gridS, TB>>>(emb_int, emb_pop, q, bq, user, itp, itn, mask, out, gridS);
}

// round 16
// speedup vs baseline: 1.0487x; 1.0487x over previous
#include <cuda_runtime.h>
#include <cuda_fp16.h>
#include <cuda_fp8.h>
#include <math.h>

// Problem constants (fixed-shape problem)
static constexpr int N_USER  = 100000;
static constexpr int N_ITEM  = 50000;
static constexpr int NN      = N_USER + N_ITEM;   // 150000
static constexpr int D       = 64;
static constexpr int ROWB    = 128;               // row bytes: 64 int + 64 pop e4m3
static constexpr int E_EDGES = 2000000;
static constexpr int BATCH   = 8192;

static constexpr int SCAN_CHUNK = 1024;
static constexpr int NB_SCAN = (NN + SCAN_CHUNK - 1) / SCAN_CHUNK;  // 147

// All fp8 buffers store 16x the true value (descaled in k_score).
// ---------------- device scratch (static globals, no allocation) -------------
__device__ int    g_dego[NN];
__device__ int    g_degi[NN];
__device__ int    g_rowptr[NN];
__device__ int    g_cursor[NN];
__device__ int    g_bsum[NB_SCAN];
__device__ int    g_dhist[256];        // degree histogram (clamped)
__device__ int    g_dcur[256];         // bucket cursors (DESCENDING-degree layout)
__device__ int    g_order[NN];         // nodes sorted by in-degree, LARGEST FIRST
__device__ int    g_csr[E_EDGES];      // src node only (norm factored out)
__device__ unsigned char g_need[NN];   // layer-3 pruning flags (sampled nodes)
__device__ unsigned char g_E[(size_t)NN * ROWB];   // 16*rdo*emb  (e4m3)
__device__ unsigned char g_A[(size_t)NN * ROWB];
__device__ unsigned char g_B[(size_t)NN * ROWB];
__device__ unsigned char g_C[(size_t)NN * ROWB];
__device__ double g_sums[4];
__device__ int    g_mask_is_u8;
__device__ unsigned g_done;            // score last-block ticket

// ---------------- helpers ----------------------------------------------------
__device__ __forceinline__ float softplus_f(float x) {
    return fmaxf(x, 0.0f) + log1pf(expf(-fabsf(x)));
}
__device__ __forceinline__ float logsig_f(float x) {
    return fminf(x, 0.0f) - log1pf(expf(-fabsf(x)));
}
// acch[8] (half2) += 16 e4m3 values packed in uint4
__device__ __forceinline__ void acc_fp8_16(__half2* acch, uint4 raw) {
    #pragma unroll
    for (int k = 0; k < 4; k++) {
        unsigned w = (&raw.x)[k];
        __half2_raw h0 = __nv_cvt_fp8x2_to_halfraw2((__nv_fp8x2_storage_t)(w & 0xFFFFu), __NV_E4M3);
        __half2_raw h1 = __nv_cvt_fp8x2_to_halfraw2((__nv_fp8x2_storage_t)(w >> 16), __NV_E4M3);
        acch[2*k]   = __hadd2(acch[2*k],   *reinterpret_cast<__half2*>(&h0));
        acch[2*k+1] = __hadd2(acch[2*k+1], *reinterpret_cast<__half2*>(&h1));
    }
}
__device__ __forceinline__ float2 fp8x2_to_float2(unsigned short v) {
    __half2_raw h = __nv_cvt_fp8x2_to_halfraw2((__nv_fp8x2_storage_t)v, __NV_E4M3);
    return __half22float2(*reinterpret_cast<__half2*>(&h));
}

// ---------------- kernels ----------------------------------------------------
// Zero degrees / flags / sums / histogram / ticket.
__global__ void k_init() {
    int i = blockIdx.x * blockDim.x + threadIdx.x;
    if (i < NN) { g_dego[i] = 0; g_degi[i] = 0; g_need[i] = 0; }
    if (i < 256) g_dhist[i] = 0;
    if (i < 4)  g_sums[i] = 0.0;
    if (i == 0) { g_mask_is_u8 = 0; g_done = 0; }
}

// Degree counting + mask-layout detect + layer-3 need flags.
__global__ void k_degree(const int* __restrict__ es, const int* __restrict__ ed,
                         const unsigned char* __restrict__ m,
                         const int* __restrict__ user, const int* __restrict__ itp,
                         const int* __restrict__ itn) {
    int i = blockIdx.x * blockDim.x + threadIdx.x;
    if (i < BATCH) {
        if ((i & 3) && m[i]) atomicOr(&g_mask_is_u8, 1);
        g_need[user[i]] = 1;
        g_need[itp[i] + N_USER] = 1;
        g_need[itn[i] + N_USER] = 1;
    }
    if (i >= E_EDGES) return;
    atomicAdd(&g_dego[es[i]], 1);
    atomicAdd(&g_degi[ed[i]], 1);
}

// Per-chunk sums of g_degi + block-aggregated degree histogram.
__global__ void k_scan_a() {
    __shared__ int sdata[256];
    __shared__ int shist[256];
    int base = blockIdx.x * SCAN_CHUNK;
    int t = threadIdx.x;
    shist[t] = 0;
    __syncthreads();
    int s = 0;
    #pragma unroll
    for (int j = 0; j < 4; j++) {
        int idx = base + t * 4 + j;
        if (idx < NN) {
            int d = g_degi[idx];
            s += d;
            atomicAdd(&shist[min(d, 255)], 1);
        }
    }
    sdata[t] = s;
    __syncthreads();
    for (int off = 128; off > 0; off >>= 1) {
        if (t < off) sdata[t] += sdata[t + off];
        __syncthreads();
    }
    if (t == 0) g_bsum[blockIdx.x] = sdata[0];
    if (shist[t]) atomicAdd(&g_dhist[t], shist[t]);
}

// Blocks [0, NB_SCAN) build rowptr/cursor; block NB_SCAN scans the degree
// histogram into DESCENDING (LPT) bucket cursors.
__global__ void k_scan_bc() {
    __shared__ int sb[256];
    __shared__ int sdata[256];
    int t = threadIdx.x;

    if (blockIdx.x < NB_SCAN) {
        sb[t] = (t < NB_SCAN) ? g_bsum[t] : 0;
        __syncthreads();
        for (int off = 1; off < 256; off <<= 1) {
            int tmp = (t >= off) ? sb[t - off] : 0;
            __syncthreads();
            sb[t] += tmp;
            __syncthreads();
        }
        int boff = (blockIdx.x == 0) ? 0 : sb[blockIdx.x - 1];

        int base = blockIdx.x * SCAN_CHUNK;
        int v[4];
        int tsum = 0;
        #pragma unroll
        for (int j = 0; j < 4; j++) {
            int idx = base + t * 4 + j;
            v[j] = (idx < NN) ? g_degi[idx] : 0;
            tsum += v[j];
        }
        sdata[t] = tsum;
        __syncthreads();
        for (int off = 1; off < 256; off <<= 1) {
            int tmp = (t >= off) ? sdata[t - off] : 0;
            __syncthreads();
            sdata[t] += tmp;
            __syncthreads();
        }
        int run = sdata[t] - tsum + boff;
        #pragma unroll
        for (int j = 0; j < 4; j++) {
            int idx = base + t * 4 + j;
            if (idx < NN) {
                g_rowptr[idx] = run;
                g_cursor[idx] = run;
                run += v[j];
            }
        }
    } else {
        // DESCENDING bucket layout (LPT): start(b) = total - inclusive_prefix(b).
        int v = g_dhist[t];
        sb[t] = v;
        __syncthreads();
        for (int off = 1; off < 256; off <<= 1) {
            int tmp = (t >= off) ? sb[t - off] : 0;
            __syncthreads();
            sb[t] += tmp;
            __syncthreads();
        }
        int total = sb[255];
        g_dcur[t] = total - sb[t];
    }
}

// Fused: edge placement + descending-degree node order scatter + grid-stride
// fp32 -> e4m3 (x16*rdo) conversion. The atomic-latency placement warps and
// the DRAM-streaming convert warps overlap inside one launch (disjoint HW
// resources: LTS atomic ALU vs HBM), hiding most of the convert time.
__global__ void k_place_convert(const int* __restrict__ es, const int* __restrict__ ed,
                                const float* __restrict__ ei, const float* __restrict__ ep) {
    int i = blockIdx.x * blockDim.x + threadIdx.x;
    if (i < E_EDGES) {
        int s = es[i];
        int d = ed[i];
        int pos = atomicAdd(&g_cursor[d], 1);
        g_csr[pos] = s;
    }
    if (i < NN) {
        int b = min(g_degi[i], 255);
        int pos = atomicAdd(&g_dcur[b], 1);
        g_order[pos] = i;
    }

    // convert: each item = 8 e4m3 bytes (uint2). NN*16 items, grid-stride.
    int total = NN * 16;
    for (int k = i; k < total; k += gridDim.x * blockDim.x) {
        int node = k >> 4;
        int sub  = k & 15;
        int eo   = sub * 8;       // element (=byte) offset within 128-row
        float sc = 16.0f * rsqrtf(fmaxf((float)g_dego[node], 1.0f));
        const float* s = (eo < 64) ? (ei + (size_t)node * D + eo)
                                   : (ep + (size_t)node * D + (eo - 64));
        float4 v0 = *reinterpret_cast<const float4*>(s);
        float4 v1 = *reinterpret_cast<const float4*>(s + 4);
        unsigned a0 = __nv_cvt_float2_to_fp8x2(make_float2(v0.x * sc, v0.y * sc), __NV_SATFINITE, __NV_E4M3);
        unsigned a1 = __nv_cvt_float2_to_fp8x2(make_float2(v0.z * sc, v0.w * sc), __NV_SATFINITE, __NV_E4M3);
        unsigned a2 = __nv_cvt_float2_to_fp8x2(make_float2(v1.x * sc, v1.y * sc), __NV_SATFINITE, __NV_E4M3);
        unsigned a3 = __nv_cvt_float2_to_fp8x2(make_float2(v1.z * sc, v1.w * sc), __NV_SATFINITE, __NV_E4M3);
        uint2 ow;
        ow.x = (a0 & 0xFFFFu) | (a1 << 16);
        ow.y = (a2 & 0xFFFFu) | (a3 << 16);
        *reinterpret_cast<uint2*>(g_E + (size_t)node * ROWB + eo) = ow;
    }
}

// CSR gather: 8 lanes per node, 4 nodes per warp, degree-sorted node order
// (largest-degree first — LPT). Row = 128B e4m3 (one line); each lane loads
// uint4 (16 fp8 = 16B). CSR indices loaded uniformly per group (hardware
// broadcast), NO shuffles. 8->4->1 unroll cascade (frozen inner loop form).
// prune != 0: skip nodes not in g_need.
__global__ void __launch_bounds__(256)
k_gather(const unsigned char* __restrict__ src, unsigned char* __restrict__ dst, int prune) {
    unsigned t = blockIdx.x * blockDim.x + threadIdx.x;
    unsigned warp = t >> 5;
    unsigned lane = t & 31u;
    unsigned grp  = lane >> 3;      // 0..3
    unsigned gl   = lane & 7u;      // lane within group
    unsigned idx  = warp * 4 + grp;
    if (idx >= (unsigned)NN) return;
    int node = g_order[idx];
    if (prune && !g_need[node]) return;

    const int c = (int)gl * 16;     // byte offset within 128B row

    int start = g_rowptr[node];
    int cnt   = g_degi[node];

    __half2 zz = __floats2half2_rn(0.f, 0.f);
    __half2 acch[8] = { zz, zz, zz, zz, zz, zz, zz, zz };

    int j = 0;
    // 8-wide main loop: 8 CSR loads + 8 row loads issued before accumulation.
    for (; j + 8 <= cnt; j += 8) {
        int si[8];
        #pragma unroll
        for (int u = 0; u < 8; u++) si[u] = __ldg(&g_csr[start + j + u]);
        uint4 rr[8];
        #pragma unroll
        for (int u = 0; u < 8; u++)
            rr[u] = __ldg(reinterpret_cast<const uint4*>(src + (size_t)si[u] * ROWB + c));
        #pragma unroll
        for (int u = 0; u < 8; u++) acc_fp8_16(acch, rr[u]);
    }
    // 4-wide step
    for (; j + 4 <= cnt; j += 4) {
        int s0 = __ldg(&g_csr[start + j + 0]);
        int s1 = __ldg(&g_csr[start + j + 1]);
        int s2 = __ldg(&g_csr[start + j + 2]);
        int s3 = __ldg(&g_csr[start + j + 3]);
        uint4 r0 = __ldg(reinterpret_cast<const uint4*>(src + (size_t)s0 * ROWB + c));
        uint4 r1 = __ldg(reinterpret_cast<const uint4*>(src + (size_t)s1 * ROWB + c));
        uint4 r2 = __ldg(reinterpret_cast<const uint4*>(src + (size_t)s2 * ROWB + c));
        uint4 r3 = __ldg(reinterpret_cast<const uint4*>(src + (size_t)s3 * ROWB + c));
        acc_fp8_16(acch, r0);
        acc_fp8_16(acch, r1);
        acc_fp8_16(acch, r2);
        acc_fp8_16(acch, r3);
    }
    // scalar tail
    for (; j < cnt; j++) {
        int sj = __ldg(&g_csr[start + j]);
        uint4 rv = __ldg(reinterpret_cast<const uint4*>(src + (size_t)sj * ROWB + c));
        acc_fp8_16(acch, rv);
    }

    float rs = rsqrtf(fmaxf((float)g_dego[node], 1.0f))
             * rsqrtf(fmaxf((float)g_degi[node], 1.0f));
    uint4 outw;
    #pragma unroll
    for (int k = 0; k < 4; k++) {
        float2 f0 = __half22float2(acch[2*k]);
        float2 f1 = __half22float2(acch[2*k+1]);
        unsigned o0 = __nv_cvt_float2_to_fp8x2(make_float2(f0.x * rs, f0.y * rs),
                                               __NV_SATFINITE, __NV_E4M3);
        unsigned o1 = __nv_cvt_float2_to_fp8x2(make_float2(f1.x * rs, f1.y * rs),
                                               __NV_SATFINITE, __NV_E4M3);
        (&outw.x)[k] = (o0 & 0xFFFFu) | (o1 << 16);
    }
    *reinterpret_cast<uint4*>(dst + (size_t)node * ROWB + c) = outw;
}

// One warp per triple. f-row (x4) = e0 + (sqrt(dego)/16) * (S_A + S_B + S_C).
// Dots scale by 1/16. Final reduction: last block writes the loss.
__global__ void __launch_bounds__(256)
k_score(const float* __restrict__ ei, const float* __restrict__ ep,
        const float* __restrict__ q, const float* __restrict__ bq,
        const int* __restrict__ user, const int* __restrict__ itp,
        const int* __restrict__ itn, const void* __restrict__ mask,
        float* __restrict__ out, int nblocks) {
    int t = blockIdx.x * blockDim.x + threadIdx.x;
    int w = t >> 5;
    int lane = t & 31;
    int wib = (threadIdx.x >> 5);
    __shared__ float sred[8][4];

    float s0 = 0.f, s1 = 0.f, s2 = 0.f, s3 = 0.f;
    if (w < BATCH) {
        int u  = user[w];
        int p  = itp[w];
        int n  = itn[w];

        auto rowsum = [&](const float* e, int node, int pop) -> float2 {
            size_t re = (size_t)node * D;
            size_t rh = (size_t)node * ROWB + pop * 64 + lane * 2;
            float sq = sqrtf(fmaxf((float)g_dego[node], 1.0f)) * 0.0625f;
            float2 x = reinterpret_cast<const float2*>(e + re)[lane];
            float2 fa = fp8x2_to_float2(*reinterpret_cast<const unsigned short*>(g_A + rh));
            float2 fb = fp8x2_to_float2(*reinterpret_cast<const unsigned short*>(g_B + rh));
            float2 fc = fp8x2_to_float2(*reinterpret_cast<const unsigned short*>(g_C + rh));
            return make_float2(x.x + sq * (fa.x + fb.x + fc.x),
                               x.y + sq * (fa.y + fb.y + fc.y));
        };

        int np = p + N_USER;
        int nn = n + N_USER;
        float2 a  = rowsum(ei, u, 0);
        float2 bb = rowsum(ep, u, 1);
        float2 cp = rowsum(ei, np, 0);
        float2 dp = rowsum(ep, np, 1);
        float2 cn = rowsum(ei, nn, 0);
        float2 dn = rowsum(ep, nn, 1);

        float pint = a.x * cp.x + a.y * cp.y;
        float nint = a.x * cn.x + a.y * cn.y;
        float ppop = bb.x * dp.x + bb.y * dp.y;
        float npop = bb.x * dn.x + bb.y * dn.y;

        #pragma unroll
        for (int o = 16; o > 0; o >>= 1) {
            pint += __shfl_xor_sync(0xffffffffu, pint, o);
            nint += __shfl_xor_sync(0xffffffffu, nint, o);
            ppop += __shfl_xor_sync(0xffffffffu, ppop, o);
            npop += __shfl_xor_sync(0xffffffffu, npop, o);
        }

        if (lane == 0) {
            const float inv16 = 0.0625f;
            pint *= inv16; nint *= inv16; ppop *= inv16; npop *= inv16;

            bool m;
            if (g_mask_is_u8)
                m = ((const unsigned char*)mask)[w] != 0;
            else
                m = ((const int*)mask)[w] != 0;
            float mf = m ? 1.0f : 0.0f;
            float nmf = 1.0f - mf;

            s0 = mf  * logsig_f(pint - nint);
            s1 = mf  * logsig_f(npop - ppop);
            s2 = nmf * logsig_f(ppop - npop);

            float popp = softplus_f(q[p]) + softplus_f(bq[p]);
            float popn = softplus_f(q[n]) + softplus_f(bq[n]);
            float ptot = pint + ppop;
            float ntot = nint + npop;
            s3 = logsig_f(tanhf(popp) * ptot - tanhf(popn) * ntot);
        }
    }
    if (lane == 0) {
        sred[wib][0] = s0; sred[wib][1] = s1; sred[wib][2] = s2; sred[wib][3] = s3;
    }
    __syncthreads();
    if (threadIdx.x < 4) {
        float tsum = 0.f;
        #pragma unroll
        for (int k = 0; k < 8; k++) tsum += sred[k][threadIdx.x];
        atomicAdd(&g_sums[threadIdx.x], (double)tsum);
    }
    // last-block ticket writes the final loss
    __syncthreads();
    if (threadIdx.x == 0) {
        __threadfence();
        unsigned ticket = atomicAdd(&g_done, 1u);
        if (ticket == (unsigned)(nblocks - 1)) {
            double invB = 1.0 / (double)BATCH;
            double loss_int  = -g_sums[0] * invB;
            double loss_pop  = (-g_sums[1] + g_sums[2]) * invB;
            double loss_tide = -g_sums[3] * invB;
            out[0] = (float)(0.1 * loss_int + 0.1 * loss_pop + 0.2 * loss_tide);
        }
    }
}

// ---------------- launch ------------------------------------------------------
extern "C" void kernel_launch(void* const* d_in, const int* in_sizes, int n_in,
                              void* d_out, int out_size) {
    const float* emb_int = (const float*)d_in[0];
    const float* emb_pop = (const float*)d_in[1];
    const float* q       = (const float*)d_in[2];
    const float* bq      = (const float*)d_in[3];
    const int*   user    = (const int*)d_in[4];
    const int*   itp     = (const int*)d_in[5];
    const int*   itn     = (const int*)d_in[6];
    const void*  mask    = d_in[7];
    const int*   es      = (const int*)d_in[8];
    const int*   ed      = (const int*)d_in[9];
    float* out = (float*)d_out;

    const int TB = 256;
    int gridE  = (E_EDGES + TB - 1) / TB;
    int gridN  = (NN + TB - 1) / TB;
    long long warpsG = (NN + 3) / 4;
    int gridG  = (int)((warpsG * 32 + TB - 1) / TB);
    int gridS  = (BATCH * 32 + TB - 1) / TB;

    unsigned char *E, *A, *B, *C;
    cudaGetSymbolAddress((void**)&E, g_E);
    cudaGetSymbolAddress((void**)&A, g_A);
    cudaGetSymbolAddress((void**)&B, g_B);
    cudaGetSymbolAddress((void**)&C, g_C);

    k_init<<<gridN, TB>>>();
    k_degree<<<gridE, TB>>>(es, ed, (const unsigned char*)mask, user, itp, itn);
    k_scan_a<<<NB_SCAN, 256>>>();
    k_scan_bc<<<NB_SCAN + 1, 256>>>();
    k_place_convert<<<gridE, TB>>>(es, ed, emb_int, emb_pop);

    k_gather<<<gridG, TB>>>(E, A, 0);   // layer 1
    k_gather<<<gridG, TB>>>(A, B, 0);   // layer 2
    k_gather<<<gridG, TB>>>(B, C, 1);   // layer 3 (need-pruned)

    k_score<<<gridS, TB>>>(emb_int, emb_pop, q, bq, user, itp, itn, mask, out, gridS);
}